// round 1
// baseline (speedup 1.0000x reference)
#include <cuda_runtime.h>
#include <cstdint>

// Max-unpool scatter with DETERMINISTIC last-index-wins collision semantics
// (matches XLA-CPU / numpy .at[].set ordering).
//
// Strategy:
//   scratch[j] : u64, packed key = ((i+1) << 32) | f32_bits(x[i])
//   K1: zero scratch (205 MB, vectorized 16B stores)
//   K2: for each input i: atomicMax(&scratch[pos[i]], key(i))
//       -> unique i means high-word strictly orders; max == largest i == "last set"
//   K3: out[j] = __uint_as_float((u32)scratch[j])
//       -> empty slot key==0 unpacks to 0.0f: compact pass doubles as output zeroing.

#define N_OUT_CONST 25690112  // 32*112*112*64

__device__ unsigned long long g_keyval[N_OUT_CONST];

__global__ void zero_scratch_kernel(int count2) {
    int idx = blockIdx.x * blockDim.x + threadIdx.x;
    if (idx < count2) {
        ulonglong2 z;
        z.x = 0ull; z.y = 0ull;
        reinterpret_cast<ulonglong2*>(g_keyval)[idx] = z;
    }
}

__device__ __forceinline__ void scatter_one(int i, int p, float v) {
    unsigned long long key =
        (static_cast<unsigned long long>(static_cast<unsigned int>(i + 1)) << 32) |
        static_cast<unsigned long long>(__float_as_uint(v));
    atomicMax(&g_keyval[p], key);
}

__global__ void scatter_kernel(const float4* __restrict__ x4,
                               const int4* __restrict__ p4,
                               int n4, int n) {
    int t = blockIdx.x * blockDim.x + threadIdx.x;
    if (t < n4) {
        float4 xv = x4[t];
        int4   pv = p4[t];
        int base = t * 4;
        scatter_one(base + 0, pv.x, xv.x);
        scatter_one(base + 1, pv.y, xv.y);
        scatter_one(base + 2, pv.z, xv.z);
        scatter_one(base + 3, pv.w, xv.w);
    }
    // Tail (n not divisible by 4): handled by the first few threads of block 0.
    int tail_start = n4 * 4;
    int rem = n - tail_start;
    if (blockIdx.x == 0 && threadIdx.x < rem) {
        int i = tail_start + threadIdx.x;
        const float* x = reinterpret_cast<const float*>(x4);
        const int*   p = reinterpret_cast<const int*>(p4);
        scatter_one(i, p[i], x[i]);
    }
}

__global__ void compact_kernel(float* __restrict__ out, int count4) {
    int t = blockIdx.x * blockDim.x + threadIdx.x;
    if (t < count4) {
        const ulonglong2* s2 = reinterpret_cast<const ulonglong2*>(g_keyval);
        ulonglong2 a = s2[2 * t];
        ulonglong2 b = s2[2 * t + 1];
        float4 o;
        o.x = __uint_as_float(static_cast<unsigned int>(a.x));
        o.y = __uint_as_float(static_cast<unsigned int>(a.y));
        o.z = __uint_as_float(static_cast<unsigned int>(b.x));
        o.w = __uint_as_float(static_cast<unsigned int>(b.y));
        reinterpret_cast<float4*>(out)[t] = o;
    }
}

extern "C" void kernel_launch(void* const* d_in, const int* in_sizes, int n_in,
                              void* d_out, int out_size) {
    const float* x  = reinterpret_cast<const float*>(d_in[0]);
    const int* pos  = reinterpret_cast<const int*>(d_in[1]);
    float* out      = reinterpret_cast<float*>(d_out);

    int n = in_sizes[0];          // 6,422,528
    int n4 = n / 4;
    int count2 = out_size / 2;    // u64 pairs (out_size = 25,690,112, even)
    int count4 = out_size / 4;

    const int T = 256;

    // K1: zero the 64-bit scratch (must run every launch — graph replays).
    zero_scratch_kernel<<<(count2 + T - 1) / T, T>>>(count2);

    // K2: deterministic last-index-wins scatter via packed atomicMax.
    scatter_kernel<<<(n4 + T - 1) / T, T>>>(
        reinterpret_cast<const float4*>(x),
        reinterpret_cast<const int4*>(pos),
        n4, n);

    // K3: unpack low word -> output (empty slots become 0.0f).
    compact_kernel<<<(count4 + T - 1) / T, T>>>(out, count4);
}

// round 2
// speedup vs baseline: 1.6798x; 1.6798x over previous
#include <cuda_runtime.h>
#include <cstdint>

// Max-unpool scatter, deterministic last-index-wins (matches reference).
//
// Round-2 scheme: 32-bit winner-index scratch (102.8 MB -> L2-resident).
//   K1: zero scratch (103 MB, 16B stores)
//   K2: for each input i: atomicMax(&scratch[pos[i]], i+1)   (pos read only,
//       spread-address 32-bit REDG.MAX hitting L2-resident lines)
//   K3: out[j] = w ? x[w-1] : 0   (scratch read ~L2-hit, x gather L2-cached,
//       out written sequentially; doubles as output zeroing)

#define N_OUT_CONST 25690112  // 32*112*112*64

__device__ unsigned int g_winner[N_OUT_CONST];

__global__ void zero_scratch_kernel(int count4) {
    int idx = blockIdx.x * blockDim.x + threadIdx.x;
    if (idx < count4) {
        uint4 z = make_uint4(0u, 0u, 0u, 0u);
        reinterpret_cast<uint4*>(g_winner)[idx] = z;
    }
}

__global__ void scatter_kernel(const int4* __restrict__ p4, int n4, int n) {
    int t = blockIdx.x * blockDim.x + threadIdx.x;
    if (t < n4) {
        int4 pv = p4[t];
        unsigned int base = (unsigned int)(t * 4);
        atomicMax(&g_winner[pv.x], base + 1u);
        atomicMax(&g_winner[pv.y], base + 2u);
        atomicMax(&g_winner[pv.z], base + 3u);
        atomicMax(&g_winner[pv.w], base + 4u);
    }
    // Tail (n % 4 != 0): first threads of block 0.
    int tail_start = n4 * 4;
    int rem = n - tail_start;
    if (blockIdx.x == 0 && threadIdx.x < rem) {
        int i = tail_start + threadIdx.x;
        const int* p = reinterpret_cast<const int*>(p4);
        atomicMax(&g_winner[p[i]], (unsigned int)(i + 1));
    }
}

__global__ void compact_kernel(float* __restrict__ out,
                               const float* __restrict__ x,
                               int count4) {
    int t = blockIdx.x * blockDim.x + threadIdx.x;
    if (t < count4) {
        uint4 w = reinterpret_cast<const uint4*>(g_winner)[t];
        float4 o;
        o.x = w.x ? __ldg(&x[w.x - 1u]) : 0.0f;
        o.y = w.y ? __ldg(&x[w.y - 1u]) : 0.0f;
        o.z = w.z ? __ldg(&x[w.z - 1u]) : 0.0f;
        o.w = w.w ? __ldg(&x[w.w - 1u]) : 0.0f;
        reinterpret_cast<float4*>(out)[t] = o;
    }
}

extern "C" void kernel_launch(void* const* d_in, const int* in_sizes, int n_in,
                              void* d_out, int out_size) {
    const float* x = reinterpret_cast<const float*>(d_in[0]);
    const int* pos = reinterpret_cast<const int*>(d_in[1]);
    float* out     = reinterpret_cast<float*>(d_out);

    int n = in_sizes[0];        // 6,422,528
    int n4 = n / 4;
    int count4 = out_size / 4;  // 6,422,528 (out_size divisible by 4)

    const int T = 256;

    // K1: zero the 32-bit winner scratch; leaves it dirty-resident in L2.
    zero_scratch_kernel<<<(count4 + T - 1) / T, T>>>(count4);

    // K2: deterministic last-index-wins via 32-bit atomicMax (index only).
    scatter_kernel<<<(n4 + T - 1) / T, T>>>(
        reinterpret_cast<const int4*>(pos), n4, n);

    // K3: gather winners' values, zero-fill empties, sequential out write.
    compact_kernel<<<(count4 + T - 1) / T, T>>>(out, x, count4);
}